// round 2
// baseline (speedup 1.0000x reference)
#include <cuda_runtime.h>
#include <math.h>

// ---------------------------------------------------------------------------
// AvULoss: N=2^21 rows, C=32.
// Per row: softmax max-prob (= 1/S after max-shift), argmax, predictive
// entropy unc = log S - (sum e_i * d_i)/S, then 4 masked weighted sums,
// final scalar loss = -log((n_ac+n_iu)/(sum+eps)+eps).
// NOTE: labels arrive as int32 (JAX x64 disabled downcasts the int64 randint).
// ---------------------------------------------------------------------------

#define C 32
#define BLOCK 256
#define ROW_STRIDE 33   // 33-float smem row stride -> conflict-free LDS/STS

__device__ double g_acc[4];

__global__ void avu_init_kernel() {
    if (threadIdx.x < 4) g_acc[threadIdx.x] = 0.0;
}

__global__ __launch_bounds__(BLOCK)
void avu_main_kernel(const float* __restrict__ logits,
                     const int* __restrict__ labels,
                     const float* __restrict__ unc_th_p)
{
    __shared__ float srow[BLOCK * ROW_STRIDE];
    __shared__ float sred[32];

    const int tid = threadIdx.x;
    const long long rowBase = (long long)blockIdx.x * BLOCK;

    // ---- Stage logits through smem: coalesced float4 gmem loads ----
    const float4* __restrict__ in4 =
        (const float4*)logits + (long long)blockIdx.x * (BLOCK * C / 4);
#pragma unroll
    for (int it = 0; it < (BLOCK * C / 4) / BLOCK; ++it) {
        int i = tid + it * BLOCK;            // float4 index within block tile
        float4 v = in4[i];
        int r = i >> 3;                       // row within tile (8 float4/row)
        int c = (i & 7) << 2;                 // starting column
        float* p = &srow[r * ROW_STRIDE + c];
        p[0] = v.x; p[1] = v.y; p[2] = v.z; p[3] = v.w;
    }
    __syncthreads();

    // ---- Pull this thread's row into registers ----
    float x[C];
#pragma unroll
    for (int j = 0; j < C; ++j) x[j] = srow[tid * ROW_STRIDE + j];

    // ---- max + argmax (strict > keeps first occurrence, matches jnp.argmax) ----
    float m = x[0];
    int am = 0;
#pragma unroll
    for (int j = 1; j < C; ++j) {
        if (x[j] > m) { m = x[j]; am = j; }
    }

    // ---- exp pass: S = sum e, dot = sum e*d ----
    float S = 0.f, dot = 0.f;
#pragma unroll
    for (int j = 0; j < C; ++j) {
        float d = x[j] - m;
        float e = __expf(d);
        S += e;
        dot = __fmaf_rn(e, d, dot);
    }

    float invS = __frcp_rn(S);
    float conf = invS;                       // max softmax prob = exp(0)/S
    float unc  = __logf(S) - dot * invS;     // predictive entropy

    int lab = labels[rowBase + tid];
    bool accurate = (lab == am);
    float th = __ldg(unc_th_p);
    bool certain = (unc <= th);
    float t = tanhf(unc);

    float w_conf = accurate ? conf : (1.f - conf);
    float w_t    = certain ? (1.f - t) : t;
    float w      = w_conf * w_t;
    int cat = (accurate ? 0 : 2) + (certain ? 0 : 1);

    float v0 = (cat == 0) ? w : 0.f;
    float v1 = (cat == 1) ? w : 0.f;
    float v2 = (cat == 2) ? w : 0.f;
    float v3 = (cat == 3) ? w : 0.f;

    // ---- warp reduction of the 4 partial sums ----
#pragma unroll
    for (int o = 16; o > 0; o >>= 1) {
        v0 += __shfl_down_sync(0xffffffffu, v0, o);
        v1 += __shfl_down_sync(0xffffffffu, v1, o);
        v2 += __shfl_down_sync(0xffffffffu, v2, o);
        v3 += __shfl_down_sync(0xffffffffu, v3, o);
    }
    const int wid = tid >> 5;
    const int lid = tid & 31;
    if (lid == 0) {
        sred[wid +  0] = v0;   // 8 warps per block
        sred[wid +  8] = v1;
        sred[wid + 16] = v2;
        sred[wid + 24] = v3;
    }
    __syncthreads();

    // ---- block -> global: 4 double atomics per block ----
    if (tid < 4) {
        double s = 0.0;
#pragma unroll
        for (int wv = 0; wv < 8; ++wv) s += (double)sred[tid * 8 + wv];
        atomicAdd(&g_acc[tid], s);
    }
}

__global__ void avu_finalize_kernel(float* __restrict__ out) {
    double n_ac = g_acc[0];
    double n_au = g_acc[1];
    double n_ic = g_acc[2];
    double n_iu = g_acc[3];
    double avu = (n_ac + n_iu) / (n_ac + n_au + n_ic + n_iu + 1e-10);
    out[0] = (float)(-log(avu + 1e-10));
}

extern "C" void kernel_launch(void* const* d_in, const int* in_sizes, int n_in,
                              void* d_out, int out_size)
{
    const float* logits = (const float*)d_in[0];
    const int*   labels = (const int*)d_in[1];
    const float* unc_th = (const float*)d_in[2];
    float* out = (float*)d_out;

    const int N = in_sizes[1];               // rows = label count (2^21)
    const int grid = N / BLOCK;              // N is a multiple of 256

    avu_init_kernel<<<1, 32>>>();
    avu_main_kernel<<<grid, BLOCK>>>(logits, labels, unc_th);
    avu_finalize_kernel<<<1, 1>>>(out);
}